// round 1
// baseline (speedup 1.0000x reference)
#include <cuda_runtime.h>

#define Bn 32
#define Tn 128
#define In 256
#define Hn 256
#define IH 512      // I + H
#define On 128

// Ping-pong hidden-state buffers (device globals: no allocation allowed).
__device__ float g_h[2][Bn * Hn];

// ---------------------------------------------------------------------------
// init: zero the F state (lives in d_out's F_T region) and h buffer 0.
// ---------------------------------------------------------------------------
__global__ void init_kernel(float* __restrict__ F)
{
    int idx = blockIdx.x * blockDim.x + threadIdx.x;
    int stride = gridDim.x * blockDim.x;
    const int total4 = Bn * Hn * IH / 4;   // 1,048,576 float4
    float4 z = make_float4(0.f, 0.f, 0.f, 0.f);
    float4* F4 = (float4*)F;
    for (int i = idx; i < total4; i += stride) F4[i] = z;
    if (idx < Bn * Hn) g_h[0][idx] = 0.f;
}

// ---------------------------------------------------------------------------
// One recurrence step. Grid: 128 blocks (2 h-rows each), 256 threads.
// Warps 0-3 -> row h0, warps 4-7 -> row h0+1; each warp handles 8 batches.
// Per-lane f-slice: float4 indices k*32+lane, k=0..3 (covers f in [0,512)).
// k=0,1 -> x_t part (global), k=2,3 -> h part (smem-staged).
// ---------------------------------------------------------------------------
__global__ __launch_bounds__(256) void step_kernel(
    const float* __restrict__ x,     // sentence (B,T,I)
    const float* __restrict__ W,     // weight  (H, IH)
    const float* __restrict__ Wl,    // weight_lambda
    const float* __restrict__ Wg,    // weight_gamma
    const float* __restrict__ bias,  // (H,)
    float* __restrict__ F,           // (B,H,IH) state, in-place
    int t)
{
    __shared__ float s_h[Bn * Hn];   // 32 KB: previous h, all batches
    __shared__ float s_w[2 * IH];    // 4 KB per array: this block's 2 rows
    __shared__ float s_l[2 * IH];
    __shared__ float s_g[2 * IH];

    const float* __restrict__ hin = g_h[t & 1];
    float* __restrict__ hout = g_h[(t & 1) ^ 1];

    const int tid = threadIdx.x;
    const int h0 = blockIdx.x * 2;

    // Stage previous h (contiguous 8192 floats) into smem.
    {
        float4* d = (float4*)s_h;
        const float4* s = (const float4*)hin;
        for (int i = tid; i < Bn * Hn / 4; i += 256) d[i] = s[i];
    }
    // Stage the block's weight rows.
    for (int i = tid; i < 2 * IH; i += 256) {
        int r = i >> 9, f = i & (IH - 1);
        int gi = (h0 + r) * IH + f;
        s_w[i] = W[gi];
        s_l[i] = Wl[gi];
        s_g[i] = Wg[gi];
    }
    __syncthreads();

    const int wid = tid >> 5, lane = tid & 31;
    const int r = wid >> 2;           // 0 or 1: which h-row this warp owns
    const int h = h0 + r;

    // Weight slices for this warp's row -> registers (reused for 8 batches).
    float4 w4[4], l4[4], g4[4];
    {
        const float4* wp = (const float4*)(s_w + r * IH);
        const float4* lp = (const float4*)(s_l + r * IH);
        const float4* gp = (const float4*)(s_g + r * IH);
#pragma unroll
        for (int k = 0; k < 4; k++) {
            int f4 = k * 32 + lane;
            w4[k] = wp[f4];
            l4[k] = lp[f4];
            g4[k] = gp[f4];
        }
    }
    const float bia = bias[h];

    for (int bi = (wid & 3); bi < Bn; bi += 4) {
        const float4* xr = (const float4*)(x + (size_t)bi * Tn * In + (size_t)t * In);
        const float4* hr = (const float4*)(s_h + bi * Hn);
        float4* Frow = (float4*)(F + (size_t)(bi * Hn + h) * IH);

        float4 in4[4], Fv[4];
        float dot = 0.f, ss = 0.f;
#pragma unroll
        for (int k = 0; k < 4; k++) {
            int f4 = k * 32 + lane;
            in4[k] = (k < 2) ? xr[f4] : hr[f4 - 64];
            Fv[k] = Frow[f4];
            float twx = w4[k].x + Fv[k].x;
            float twy = w4[k].y + Fv[k].y;
            float twz = w4[k].z + Fv[k].z;
            float tww = w4[k].w + Fv[k].w;
            dot += in4[k].x * twx + in4[k].y * twy + in4[k].z * twz + in4[k].w * tww;
            ss  += twx * twx + twy * twy + twz * twz + tww * tww;
        }
#pragma unroll
        for (int o = 16; o > 0; o >>= 1) {
            dot += __shfl_xor_sync(0xffffffffu, dot, o);
            ss  += __shfl_xor_sync(0xffffffffu, ss, o);
        }
        float rn = 1.0f / (sqrtf(ss) + 1e-16f);
        float hn = tanhf(dot + bia) * rn;
#pragma unroll
        for (int k = 0; k < 4; k++) {
            int f4 = k * 32 + lane;
            float4 o;
            o.x = l4[k].x * (Fv[k].x * rn) + g4[k].x * (in4[k].x * hn);
            o.y = l4[k].y * (Fv[k].y * rn) + g4[k].y * (in4[k].y * hn);
            o.z = l4[k].z * (Fv[k].z * rn) + g4[k].z * (in4[k].z * hn);
            o.w = l4[k].w * (Fv[k].w * rn) + g4[k].w * (in4[k].w * hn);
            Frow[f4] = o;
        }
        if (lane == 0) hout[bi * Hn + h] = hn;
    }
}

// ---------------------------------------------------------------------------
// Epilogue: tag_space = h_T @ W_out^T + b_out; copy h_T.
// Grid: 32 blocks (batch), 128 threads (4 warps). Warp w handles outputs
// o = w, w+4, ...; lanes reduce over the 256-dim dot product.
// ---------------------------------------------------------------------------
__global__ void final_kernel(const float* __restrict__ Wout,
                             const float* __restrict__ bout,
                             float* __restrict__ out)
{
    __shared__ float s_h[Hn];
    const int b = blockIdx.x, tid = threadIdx.x;
    const float* hrow = g_h[0] + b * Hn;   // T=128 even -> final h in buffer 0
    for (int i = tid; i < Hn; i += 128) s_h[i] = hrow[i];
    __syncthreads();

    const int wid = tid >> 5, lane = tid & 31;
    for (int o = wid; o < On; o += 4) {
        const float4* wr = (const float4*)(Wout + o * Hn);
        const float4* hv4 = (const float4*)s_h;
        float acc = 0.f;
#pragma unroll
        for (int k = 0; k < 2; k++) {
            int j4 = k * 32 + lane;
            float4 w = wr[j4];
            float4 hv = hv4[j4];
            acc += w.x * hv.x + w.y * hv.y + w.z * hv.z + w.w * hv.w;
        }
#pragma unroll
        for (int off = 16; off > 0; off >>= 1)
            acc += __shfl_xor_sync(0xffffffffu, acc, off);
        if (lane == 0) out[b * On + o] = acc + bout[o];
    }
    // copy h_T into output slot [4096 : 12288)
    for (int i = tid; i < Hn; i += 128) out[Bn * On + b * Hn + i] = s_h[i];
}

// ---------------------------------------------------------------------------
// Inputs (metadata order): sentence, weight_lambda, weight_gamma, weight,
// bias, W_out, b_out. Output: [tag(4096) | h_T(8192) | F_T(4194304)].
// F state lives directly in d_out's F_T region (updated in place each step).
// ---------------------------------------------------------------------------
extern "C" void kernel_launch(void* const* d_in, const int* in_sizes, int n_in,
                              void* d_out, int out_size)
{
    const float* sentence = (const float*)d_in[0];
    const float* Wl   = (const float*)d_in[1];
    const float* Wg   = (const float*)d_in[2];
    const float* W    = (const float*)d_in[3];
    const float* bias = (const float*)d_in[4];
    const float* Wout = (const float*)d_in[5];
    const float* bout = (const float*)d_in[6];
    float* out = (float*)d_out;
    float* F = out + Bn * On + Bn * Hn;   // offset 12288 floats

    init_kernel<<<256, 256>>>(F);
    for (int t = 0; t < Tn; t++)
        step_kernel<<<Hn / 2, 256>>>(sentence, W, Wl, Wg, bias, F, t);
    final_kernel<<<Bn, 128>>>(Wout, bout, out);
}

// round 2
// speedup vs baseline: 2.5552x; 2.5552x over previous
#include <cuda_runtime.h>

#define Bn 32
#define Tn 128
#define In 256
#define Hn 256
#define IH 512
#define On 128
#define NBLK 128      // persistent blocks; 128 KB smem each => 1/SM => all co-resident
#define NTHR 512      // 16 warps

__device__ float g_h[2][Bn * Hn];   // ping-pong hidden state
__device__ unsigned g_bar;          // grid barrier counter

// ---------------------------------------------------------------------------
__global__ void init_kernel()
{
    int i = blockIdx.x * blockDim.x + threadIdx.x;
    if (i == 0) g_bar = 0u;
    for (int k = i; k < Bn * Hn; k += gridDim.x * blockDim.x) g_h[0][k] = 0.f;
}

// ---------------------------------------------------------------------------
// Persistent kernel: block owns h-rows {2*bid, 2*bid+1} x all 32 batches.
// F slice (64 rows x 512 floats = 128 KB) lives in dynamic smem for all T.
// Warp w: r = w>>3 (which h-row), bi0 = w&7; handles batches bi0+{0,8,16,24}.
// Per-lane f-slice: float4 idx f4 = k*32+lane, k=0..3 (f in [0,512)).
// ---------------------------------------------------------------------------
__global__ __launch_bounds__(NTHR, 1) void persist_kernel(
    const float* __restrict__ x,
    const float* __restrict__ Wl,
    const float* __restrict__ Wg,
    const float* __restrict__ W,
    const float* __restrict__ bias,
    const float* __restrict__ Wout,
    const float* __restrict__ bout,
    float* __restrict__ out)
{
    extern __shared__ float F_sm[];            // 64 * 512 floats
    float4* __restrict__ F4 = (float4*)F_sm;   // [64][128]

    const int tid  = threadIdx.x;
    const int wid  = tid >> 5, lane = tid & 31;
    const int r    = wid >> 3;
    const int bi0  = wid & 7;
    const int h    = blockIdx.x * 2 + r;

    // Pin this warp's weight-row slices in registers for the entire kernel.
    float4 w4[4], l4[4], g4[4];
    {
        const float4* Wp  = (const float4*)(W  + (size_t)h * IH);
        const float4* Lp  = (const float4*)(Wl + (size_t)h * IH);
        const float4* Gp  = (const float4*)(Wg + (size_t)h * IH);
#pragma unroll
        for (int k = 0; k < 4; k++) {
            int f4 = k * 32 + lane;
            w4[k] = __ldg(Wp + f4);
            l4[k] = __ldg(Lp + f4);
            g4[k] = __ldg(Gp + f4);
        }
    }
    const float bia = __ldg(bias + h);

    // Zero the F slice.
    {
        float4 z = make_float4(0.f, 0.f, 0.f, 0.f);
        for (int i = tid; i < 64 * 128; i += NTHR) F4[i] = z;
    }
    __syncthreads();

    for (int t = 0; t < Tn; t++) {
        const float4* __restrict__ hin = (const float4*)g_h[t & 1];
        float* __restrict__ hout = g_h[(t & 1) ^ 1];

#pragma unroll
        for (int u = 0; u < 4; u++) {
            const int bi = bi0 + u * 8;
            const float4* __restrict__ xr = (const float4*)(x + ((size_t)bi * Tn + t) * In);
            const float4* __restrict__ hr = hin + bi * (Hn / 4);
            float4* __restrict__ Fr = F4 + (r * 32 + bi) * (IH / 4);

            float4 in4[4], Fv[4];
            float dot = 0.f, ss = 0.f;
#pragma unroll
            for (int k = 0; k < 4; k++) {
                int f4 = k * 32 + lane;
                in4[k] = (k < 2) ? __ldg(xr + f4) : __ldcg(hr + (f4 - 64));
                Fv[k] = Fr[f4];
                float twx = w4[k].x + Fv[k].x;
                float twy = w4[k].y + Fv[k].y;
                float twz = w4[k].z + Fv[k].z;
                float tww = w4[k].w + Fv[k].w;
                dot += in4[k].x * twx + in4[k].y * twy + in4[k].z * twz + in4[k].w * tww;
                ss  += twx * twx + twy * twy + twz * twz + tww * tww;
            }
#pragma unroll
            for (int o = 16; o > 0; o >>= 1) {
                dot += __shfl_xor_sync(0xffffffffu, dot, o);
                ss  += __shfl_xor_sync(0xffffffffu, ss, o);
            }
            float rn = 1.0f / (sqrtf(ss) + 1e-16f);
            float hn = tanhf(dot + bia) * rn;
#pragma unroll
            for (int k = 0; k < 4; k++) {
                int f4 = k * 32 + lane;
                float4 o;
                o.x = l4[k].x * (Fv[k].x * rn) + g4[k].x * (in4[k].x * hn);
                o.y = l4[k].y * (Fv[k].y * rn) + g4[k].y * (in4[k].y * hn);
                o.z = l4[k].z * (Fv[k].z * rn) + g4[k].z * (in4[k].z * hn);
                o.w = l4[k].w * (Fv[k].w * rn) + g4[k].w * (in4[k].w * hn);
                Fr[f4] = o;
            }
            if (lane == 0) hout[bi * Hn + h] = hn;
        }

        // ---- grid barrier (release/acquire via L2 atomics) ----
        __threadfence();
        __syncthreads();
        if (tid == 0) {
            atomicAdd(&g_bar, 1u);
            const unsigned target = (unsigned)NBLK * (unsigned)(t + 1);
            while (atomicAdd(&g_bar, 0u) < target) __nanosleep(64);
        }
        __syncthreads();
    }

    // ---- write F state out (block-local, already synced by final barrier) ----
    float* __restrict__ Fout = out + Bn * On + Bn * Hn;
    float4* __restrict__ Fo4 = (float4*)Fout;
    for (int j = wid; j < 64; j += 16) {
        int rr = j >> 5, bb = j & 31;
        int grow = bb * Hn + blockIdx.x * 2 + rr;
#pragma unroll
        for (int k = 0; k < 4; k++) {
            int f4 = k * 32 + lane;
            Fo4[(size_t)grow * (IH / 4) + f4] = F4[j * (IH / 4) + f4];
        }
    }

    // ---- epilogue: tag_space (blocks 0-31), h_T copy (blocks 32-63) ----
    // Final h (T=128 even) is in g_h[0]; all writes fenced by last barrier.
    if (blockIdx.x < 32) {
        const int b = blockIdx.x;
        __syncthreads();                       // F_sm reads above done; reuse as h cache
        for (int i = tid; i < Hn; i += NTHR)
            F_sm[i] = __ldcg(&g_h[0][b * Hn + i]);
        __syncthreads();
        const float4* hv4 = (const float4*)F_sm;
        for (int o = wid; o < On; o += 16) {
            const float4* wr = (const float4*)(Wout + (size_t)o * Hn);
            float acc = 0.f;
#pragma unroll
            for (int k = 0; k < 2; k++) {
                int j4 = k * 32 + lane;
                float4 w = __ldg(wr + j4);
                float4 hv = hv4[j4];
                acc += w.x * hv.x + w.y * hv.y + w.z * hv.z + w.w * hv.w;
            }
#pragma unroll
            for (int off = 16; off > 0; off >>= 1)
                acc += __shfl_xor_sync(0xffffffffu, acc, off);
            if (lane == 0) out[b * On + o] = acc + __ldg(bout + o);
        }
    } else if (blockIdx.x < 64) {
        const int b = blockIdx.x - 32;
        for (int i = tid; i < Hn; i += NTHR)
            out[Bn * On + b * Hn + i] = __ldcg(&g_h[0][b * Hn + i]);
    }
}

// ---------------------------------------------------------------------------
extern "C" void kernel_launch(void* const* d_in, const int* in_sizes, int n_in,
                              void* d_out, int out_size)
{
    const float* sentence = (const float*)d_in[0];
    const float* Wl   = (const float*)d_in[1];
    const float* Wg   = (const float*)d_in[2];
    const float* W    = (const float*)d_in[3];
    const float* bias = (const float*)d_in[4];
    const float* Wout = (const float*)d_in[5];
    const float* bout = (const float*)d_in[6];
    float* out = (float*)d_out;

    const int smem = 64 * IH * sizeof(float);  // 131072
    cudaFuncSetAttribute(persist_kernel, cudaFuncAttributeMaxDynamicSharedMemorySize, smem);

    init_kernel<<<32, 256>>>();
    persist_kernel<<<NBLK, NTHR, smem>>>(sentence, Wl, Wg, W, bias, Wout, bout, out);
}

// round 3
// speedup vs baseline: 2.6451x; 1.0352x over previous
#include <cuda_runtime.h>

#define Bn 32
#define Tn 128
#define In 256
#define Hn 256
#define IH 512
#define On 128
#define NBLK 128      // persistent blocks; 128 KB smem => 1 block/SM => all co-resident
#define NTHR 512      // 16 warps

__device__ float g_h[2][Bn * Hn];   // ping-pong hidden state
__device__ unsigned g_bar;          // monotonic grid-barrier counter

// ---------------------------------------------------------------------------
__global__ void init_kernel()
{
    int i = blockIdx.x * blockDim.x + threadIdx.x;
    if (i == 0) g_bar = 0u;
    for (int k = i; k < Bn * Hn; k += gridDim.x * blockDim.x) g_h[0][k] = 0.f;
}

// ---------------------------------------------------------------------------
__device__ __forceinline__ float warp_sum(float v)
{
#pragma unroll
    for (int o = 16; o > 0; o >>= 1) v += __shfl_xor_sync(0xffffffffu, v, o);
    return v;
}
__device__ __forceinline__ float tanh_fast(float v)
{
    float r; asm("tanh.approx.f32 %0, %1;" : "=f"(r) : "f"(v)); return r;
}
__device__ __forceinline__ unsigned ld_acquire(const unsigned* p)
{
    unsigned v;
    asm volatile("ld.acquire.gpu.global.u32 %0, [%1];" : "=r"(v) : "l"(p) : "memory");
    return v;
}
__device__ __forceinline__ void red_release(unsigned* p)
{
    asm volatile("red.release.gpu.global.add.u32 [%0], 1;" :: "l"(p) : "memory");
}
__device__ __forceinline__ float d4(float4 a, float4 b)
{
    return a.x * b.x + a.y * b.y + a.z * b.z + a.w * b.w;
}

// ---------------------------------------------------------------------------
// Persistent kernel. Block owns h-rows {2*bid, 2*bid+1} x all 32 batches;
// its F slice (64 rows x 512 f) lives in smem for all 128 steps.
// Warp w: r = w>>3 (row), bi0 = w&7; batches bi0 + {0,8,16,24}.
// Lane f-slice: float4 index f4 = k*32+lane, k=0..3.
//
// Per step:
//   phase A (pre-barrier, local):  ss=||W+F||^2 -> rn, x-part of dot (per-lane)
//   wait grid barrier (h(t-1) ready)
//   phase B (critical): h-part of dot, reduce, tanh, F writeback, h store
//   arrive
// ---------------------------------------------------------------------------
__global__ __launch_bounds__(NTHR, 1) void persist_kernel(
    const float* __restrict__ x,
    const float* __restrict__ Wl,
    const float* __restrict__ Wg,
    const float* __restrict__ W,
    const float* __restrict__ bias,
    const float* __restrict__ Wout,
    const float* __restrict__ bout,
    float* __restrict__ out)
{
    extern __shared__ float F_sm[];            // 64 * 512 floats = 128 KB
    float4* __restrict__ F4 = (float4*)F_sm;   // [64][128]

    const int tid  = threadIdx.x;
    const int wid  = tid >> 5, lane = tid & 31;
    const int r    = wid >> 3;
    const int bi0  = wid & 7;
    const int h    = blockIdx.x * 2 + r;

    // Pin this warp's weight-row slices in registers for the whole kernel.
    float4 w4[4], l4[4], g4[4];
    {
        const float4* Wp = (const float4*)(W  + (size_t)h * IH);
        const float4* Lp = (const float4*)(Wl + (size_t)h * IH);
        const float4* Gp = (const float4*)(Wg + (size_t)h * IH);
#pragma unroll
        for (int k = 0; k < 4; k++) {
            int f4 = k * 32 + lane;
            w4[k] = __ldg(Wp + f4);
            l4[k] = __ldg(Lp + f4);
            g4[k] = __ldg(Gp + f4);
        }
    }
    const float bia = __ldg(bias + h);

    // Zero F slice.
    {
        float4 z = make_float4(0.f, 0.f, 0.f, 0.f);
        for (int i = tid; i < 64 * 128; i += NTHR) F4[i] = z;
    }
    __syncthreads();

    for (int t = 0; t < Tn; t++) {
        const float4* __restrict__ hin = (const float4*)g_h[t & 1];
        float* __restrict__ hout = g_h[(t & 1) ^ 1];

        float rnA[4], dxA[4];

        // ---------------- phase A: barrier-independent work ----------------
#pragma unroll
        for (int u = 0; u < 4; u++) {
            const int bi = bi0 + u * 8;
            const float4* __restrict__ xr = (const float4*)(x + ((size_t)bi * Tn + t) * In);
            const float4* __restrict__ Fr = F4 + (r * 32 + bi) * (IH / 4);

            float ss0 = 0.f, ss1 = 0.f, dx0 = 0.f, dx1 = 0.f;
#pragma unroll
            for (int k = 0; k < 4; k++) {
                int f4 = k * 32 + lane;
                float4 Fv = Fr[f4];
                float4 tw;
                tw.x = w4[k].x + Fv.x; tw.y = w4[k].y + Fv.y;
                tw.z = w4[k].z + Fv.z; tw.w = w4[k].w + Fv.w;
                if (k & 1) ss1 += d4(tw, tw); else ss0 += d4(tw, tw);
                if (k < 2) {
                    float4 xv = __ldg(xr + f4);
                    if (k & 1) dx1 += d4(xv, tw); else dx0 += d4(xv, tw);
                }
            }
            rnA[u] = rsqrtf(warp_sum(ss0 + ss1));  // 1/(||W+F||+eps), eps negligible
            dxA[u] = dx0 + dx1;                    // per-lane partial, reduced in B
        }

        // ---------------- grid barrier wait: h(t-1) ready ----------------
        if (tid == 0) {
            const unsigned target = (unsigned)NBLK * (unsigned)t;
            while (ld_acquire(&g_bar) < target) __nanosleep(32);
        }
        __syncthreads();

        // ---------------- phase B: barrier-critical work ----------------
#pragma unroll
        for (int u = 0; u < 4; u++) {
            const int bi = bi0 + u * 8;
            const float4* __restrict__ xr = (const float4*)(x + ((size_t)bi * Tn + t) * In);
            const float4* __restrict__ hr = hin + bi * (Hn / 4);
            float4* __restrict__ Fr = F4 + (r * 32 + bi) * (IH / 4);

            float4 h40 = __ldcg(hr + lane);
            float4 h41 = __ldcg(hr + 32 + lane);
            float4 Fv2 = Fr[64 + lane];
            float4 Fv3 = Fr[96 + lane];

            float4 tw2, tw3;
            tw2.x = w4[2].x + Fv2.x; tw2.y = w4[2].y + Fv2.y;
            tw2.z = w4[2].z + Fv2.z; tw2.w = w4[2].w + Fv2.w;
            tw3.x = w4[3].x + Fv3.x; tw3.y = w4[3].y + Fv3.y;
            tw3.z = w4[3].z + Fv3.z; tw3.w = w4[3].w + Fv3.w;

            float tot = warp_sum(dxA[u] + d4(h40, tw2) + d4(h41, tw3));
            const float rn = rnA[u];
            const float hn = tanh_fast(tot + bia) * rn;

            // writeback: F = l*(F*rn) + g*(in*hn)
            float4 x40 = __ldg(xr + lane);
            float4 x41 = __ldg(xr + 32 + lane);
            float4 Fv0 = Fr[lane];
            float4 Fv1 = Fr[32 + lane];
            float4 o;
            o.x = l4[0].x * (Fv0.x * rn) + g4[0].x * (x40.x * hn);
            o.y = l4[0].y * (Fv0.y * rn) + g4[0].y * (x40.y * hn);
            o.z = l4[0].z * (Fv0.z * rn) + g4[0].z * (x40.z * hn);
            o.w = l4[0].w * (Fv0.w * rn) + g4[0].w * (x40.w * hn);
            Fr[lane] = o;
            o.x = l4[1].x * (Fv1.x * rn) + g4[1].x * (x41.x * hn);
            o.y = l4[1].y * (Fv1.y * rn) + g4[1].y * (x41.y * hn);
            o.z = l4[1].z * (Fv1.z * rn) + g4[1].z * (x41.z * hn);
            o.w = l4[1].w * (Fv1.w * rn) + g4[1].w * (x41.w * hn);
            Fr[32 + lane] = o;
            o.x = l4[2].x * (Fv2.x * rn) + g4[2].x * (h40.x * hn);
            o.y = l4[2].y * (Fv2.y * rn) + g4[2].y * (h40.y * hn);
            o.z = l4[2].z * (Fv2.z * rn) + g4[2].z * (h40.z * hn);
            o.w = l4[2].w * (Fv2.w * rn) + g4[2].w * (h40.w * hn);
            Fr[64 + lane] = o;
            o.x = l4[3].x * (Fv3.x * rn) + g4[3].x * (h41.x * hn);
            o.y = l4[3].y * (Fv3.y * rn) + g4[3].y * (h41.y * hn);
            o.z = l4[3].z * (Fv3.z * rn) + g4[3].z * (h41.z * hn);
            o.w = l4[3].w * (Fv3.w * rn) + g4[3].w * (h41.w * hn);
            Fr[96 + lane] = o;

            if (lane == 0) hout[bi * Hn + h] = hn;
        }

        // ---------------- arrive ----------------
        __threadfence();
        __syncthreads();
        if (tid == 0) red_release(&g_bar);
    }

    // ---- write F state out (block-local) ----
    float* __restrict__ Fout = out + Bn * On + Bn * Hn;
    float4* __restrict__ Fo4 = (float4*)Fout;
    for (int j = wid; j < 64; j += 16) {
        int rr = j >> 5, bb = j & 31;
        int grow = bb * Hn + blockIdx.x * 2 + rr;
#pragma unroll
        for (int k = 0; k < 4; k++) {
            int f4 = k * 32 + lane;
            Fo4[(size_t)grow * (IH / 4) + f4] = F4[j * (IH / 4) + f4];
        }
    }

    // ---- epilogue (needs all blocks' final h) ----
    if (blockIdx.x < 64) {
        if (tid == 0) {
            const unsigned target = (unsigned)NBLK * (unsigned)Tn;
            while (ld_acquire(&g_bar) < target) __nanosleep(32);
        }
        __syncthreads();
    }

    if (blockIdx.x < 32) {
        const int b = blockIdx.x;
        for (int i = tid; i < Hn; i += NTHR)
            F_sm[i] = __ldcg(&g_h[0][b * Hn + i]);   // T even -> final h in buf 0
        __syncthreads();
        const float4* hv4 = (const float4*)F_sm;
        for (int o = wid; o < On; o += 16) {
            const float4* wr = (const float4*)(Wout + (size_t)o * Hn);
            float acc = 0.f;
#pragma unroll
            for (int k = 0; k < 2; k++) {
                int j4 = k * 32 + lane;
                acc += d4(__ldg(wr + j4), hv4[j4]);
            }
            acc = warp_sum(acc);
            if (lane == 0) out[b * On + o] = acc + __ldg(bout + o);
        }
    } else if (blockIdx.x < 64) {
        const int b = blockIdx.x - 32;
        for (int i = tid; i < Hn; i += NTHR)
            out[Bn * On + b * Hn + i] = __ldcg(&g_h[0][b * Hn + i]);
    }
}

// ---------------------------------------------------------------------------
extern "C" void kernel_launch(void* const* d_in, const int* in_sizes, int n_in,
                              void* d_out, int out_size)
{
    const float* sentence = (const float*)d_in[0];
    const float* Wl   = (const float*)d_in[1];
    const float* Wg   = (const float*)d_in[2];
    const float* W    = (const float*)d_in[3];
    const float* bias = (const float*)d_in[4];
    const float* Wout = (const float*)d_in[5];
    const float* bout = (const float*)d_in[6];
    float* out = (float*)d_out;

    const int smem = 64 * IH * sizeof(float);  // 131072
    cudaFuncSetAttribute(persist_kernel, cudaFuncAttributeMaxDynamicSharedMemorySize, smem);

    init_kernel<<<32, 256>>>();
    persist_kernel<<<NBLK, NTHR, smem>>>(sentence, Wl, Wg, W, bias, Wout, bout, out);
}